// round 2
// baseline (speedup 1.0000x reference)
#include <cuda_runtime.h>
#include <cstdint>
#include <cstddef>

#define DEV __device__ __forceinline__

// ---------- scratch ----------
__device__ float g_h0[32768], g_h1[32768];
__device__ float g_sv[65536];            // [att][b][j]
__device__ float g_e[32768];             // [att][s*32+b]
__device__ float g_alpha[32768];         // [att][b][s]
__device__ float g_ctx[65536];           // [att][b][k]
__device__ float g_out1[32768];          // [b][k]

DEV float to_tf32(float x) { uint32_t u; asm("cvt.rna.tf32.f32 %0,%1;" : "=r"(u) : "f"(x)); return __uint_as_float(u); }
DEV float tanh_fast(float x) { float y; asm("tanh.approx.f32 %0,%1;" : "=f"(y) : "f"(x)); return y; }
DEV float sigm(float x) { return 1.f / (1.f + expf(-x)); }
DEV void mma8(float c[4], const uint32_t a[4], const uint32_t b[2]) {
    asm volatile("mma.sync.aligned.m16n8k8.row.col.f32.tf32.tf32.f32 "
                 "{%0,%1,%2,%3},{%4,%5,%6,%7},{%8,%9},{%0,%1,%2,%3};"
                 : "+f"(c[0]), "+f"(c[1]), "+f"(c[2]), "+f"(c[3])
                 : "r"(a[0]), "r"(a[1]), "r"(a[2]), "r"(a[3]), "r"(b[0]), "r"(b[1]));
}

__global__ void zero_kernel() { int i = blockIdx.x * 256 + threadIdx.x; if (i < 32768) g_e[i] = 0.f; }

// ---------- GRU: one block per output j ----------
__global__ void gru_kernel(const float* __restrict__ Wih, const float* __restrict__ Whh,
                           const float* __restrict__ bih, const float* __restrict__ bhh,
                           const int* __restrict__ ids, const float* __restrict__ emb,
                           const float* __restrict__ hidden, int layer, float* __restrict__ out_nh) {
    const int j = blockIdx.x;
    __shared__ float w[6][1024];
    for (int k = threadIdx.x; k < 1024; k += 256) {
        w[0][k] = Wih[(size_t)j * 1024 + k];
        w[1][k] = Wih[(size_t)(1024 + j) * 1024 + k];
        w[2][k] = Wih[(size_t)(2048 + j) * 1024 + k];
        w[3][k] = Whh[(size_t)j * 1024 + k];
        w[4][k] = Whh[(size_t)(1024 + j) * 1024 + k];
        w[5][k] = Whh[(size_t)(2048 + j) * 1024 + k];
    }
    __syncthreads();
    const int lane = threadIdx.x & 31, wid = threadIdx.x >> 5;
    const float* hprev = hidden + (size_t)layer * 32768;
    float* hout = layer ? g_h1 : g_h0;
    for (int b = wid; b < 32; b += 8) {
        const float* xrow = layer ? (g_h0 + (size_t)b * 1024) : (emb + (size_t)ids[b] * 1024);
        const float* hrow = hprev + (size_t)b * 1024;
        float a0 = 0, a1 = 0, a2 = 0, a3 = 0, a4 = 0, a5 = 0;
        for (int k = lane; k < 1024; k += 32) {
            float xv = xrow[k], hv = hrow[k];
            a0 += w[0][k] * xv; a1 += w[1][k] * xv; a2 += w[2][k] * xv;
            a3 += w[3][k] * hv; a4 += w[4][k] * hv; a5 += w[5][k] * hv;
        }
        #pragma unroll
        for (int o = 16; o; o >>= 1) {
            a0 += __shfl_xor_sync(~0u, a0, o); a1 += __shfl_xor_sync(~0u, a1, o);
            a2 += __shfl_xor_sync(~0u, a2, o); a3 += __shfl_xor_sync(~0u, a3, o);
            a4 += __shfl_xor_sync(~0u, a4, o); a5 += __shfl_xor_sync(~0u, a5, o);
        }
        if (lane == 0) {
            float r = sigm(a0 + a3 + bih[j] + bhh[j]);
            float z = sigm(a1 + a4 + bih[1024 + j] + bhh[1024 + j]);
            float n = tanhf(a2 + bih[2048 + j] + r * (a5 + bhh[2048 + j]));
            float h = (1.f - z) * n + z * hrow[j];
            hout[b * 1024 + j] = h;
            out_nh[layer * 32768 + b * 1024 + j] = h;
        }
    }
}

// ---------- state-part of fc1 (+bias) ----------
__global__ void sv_kernel(const float* __restrict__ fc1a, const float* __restrict__ fc1ab,
                          const float* __restrict__ fc1p, const float* __restrict__ fc1pb) {
    const int att = blockIdx.y, j0 = blockIdx.x * 4;
    const float* W = att ? fc1p : fc1a;
    const float* bias = att ? fc1pb : fc1ab;
    __shared__ float ws[4][2048];
    for (int r = 0; r < 4; r++)
        for (int k = threadIdx.x; k < 2048; k += 256)
            ws[r][k] = W[(size_t)(j0 + r) * 3072 + k];
    __syncthreads();
    const int lane = threadIdx.x & 31, wid = threadIdx.x >> 5;
    for (int bi = 0; bi < 4; bi++) {
        const int b = wid * 4 + bi;
        const float* s0 = g_h0 + (size_t)b * 1024;
        const float* s1 = g_h1 + (size_t)b * 1024;
        float a0 = 0, a1 = 0, a2 = 0, a3 = 0;
        for (int k = lane; k < 1024; k += 32) {
            float v0 = s0[k], v1 = s1[k];
            a0 += ws[0][k] * v0 + ws[0][1024 + k] * v1;
            a1 += ws[1][k] * v0 + ws[1][1024 + k] * v1;
            a2 += ws[2][k] * v0 + ws[2][1024 + k] * v1;
            a3 += ws[3][k] * v0 + ws[3][1024 + k] * v1;
        }
        #pragma unroll
        for (int o = 16; o; o >>= 1) {
            a0 += __shfl_xor_sync(~0u, a0, o); a1 += __shfl_xor_sync(~0u, a1, o);
            a2 += __shfl_xor_sync(~0u, a2, o); a3 += __shfl_xor_sync(~0u, a3, o);
        }
        if (lane == 0) {
            float* d = g_sv + att * 32768 + b * 1024 + j0;
            d[0] = a0 + bias[j0]; d[1] = a1 + bias[j0 + 1];
            d[2] = a2 + bias[j0 + 2]; d[3] = a3 + bias[j0 + 3];
        }
    }
}

// ---------- big fused GEMM + tanh/fc2 epilogue -> e ----------
__global__ __launch_bounds__(256) void big_att_kernel(
    const float* __restrict__ enc, const float* __restrict__ encp,
    const float* __restrict__ fc1a, const float* __restrict__ fc1p,
    const float* __restrict__ fc2a, const float* __restrict__ fc2p) {
    const int att = blockIdx.z;
    const float* __restrict__ A = att ? encp : enc;
    const float* __restrict__ W = att ? fc1p : fc1a;
    const float* __restrict__ fc2 = att ? fc2p : fc2a;
    const int m0 = blockIdx.y * 128, n0 = blockIdx.x * 128;

    __shared__ float sA[128 * 36], sB[128 * 36];
    const int tid = threadIdx.x, lane = tid & 31, wid = tid >> 5;
    const int wm = wid >> 2, wn = wid & 3, g = lane >> 2, tg = lane & 3;

    float acc[4][4][4];
    #pragma unroll
    for (int i = 0; i < 4; i++)
        #pragma unroll
        for (int j = 0; j < 4; j++) { acc[i][j][0] = acc[i][j][1] = acc[i][j][2] = acc[i][j][3] = 0.f; }

    const int ldrow = tid >> 3, ldc = (tid & 7) * 4;
    const float* Ap = A + (size_t)(m0 + ldrow) * 1024 + ldc;
    const float* Wp = W + (size_t)(n0 + ldrow) * 3072 + 2048 + ldc;

    float4 ra[4], rb[4];
    #pragma unroll
    for (int i = 0; i < 4; i++) {
        ra[i] = *(const float4*)(Ap + (size_t)i * 32 * 1024);
        rb[i] = *(const float4*)(Wp + (size_t)i * 32 * 3072);
    }
    for (int t = 0; t < 32; t++) {
        #pragma unroll
        for (int i = 0; i < 4; i++) {
            float4 a = ra[i], b = rb[i];
            a.x = to_tf32(a.x); a.y = to_tf32(a.y); a.z = to_tf32(a.z); a.w = to_tf32(a.w);
            b.x = to_tf32(b.x); b.y = to_tf32(b.y); b.z = to_tf32(b.z); b.w = to_tf32(b.w);
            *(float4*)&sA[(ldrow + i * 32) * 36 + ldc] = a;
            *(float4*)&sB[(ldrow + i * 32) * 36 + ldc] = b;
        }
        __syncthreads();
        if (t + 1 < 32) {
            #pragma unroll
            for (int i = 0; i < 4; i++) {
                ra[i] = *(const float4*)(Ap + (size_t)i * 32 * 1024 + (t + 1) * 32);
                rb[i] = *(const float4*)(Wp + (size_t)i * 32 * 3072 + (t + 1) * 32);
            }
        }
        #pragma unroll
        for (int kk = 0; kk < 32; kk += 8) {
            uint32_t af[4][4], bf[4][2];
            #pragma unroll
            for (int mi = 0; mi < 4; mi++) {
                const int r = (wm * 64 + mi * 16 + g) * 36 + kk + tg;
                af[mi][0] = __float_as_uint(sA[r]);
                af[mi][1] = __float_as_uint(sA[r + 8 * 36]);
                af[mi][2] = __float_as_uint(sA[r + 4]);
                af[mi][3] = __float_as_uint(sA[r + 8 * 36 + 4]);
            }
            #pragma unroll
            for (int ni = 0; ni < 4; ni++) {
                const int r = (wn * 32 + ni * 8 + g) * 36 + kk + tg;
                bf[ni][0] = __float_as_uint(sB[r]);
                bf[ni][1] = __float_as_uint(sB[r + 4]);
            }
            #pragma unroll
            for (int mi = 0; mi < 4; mi++)
                #pragma unroll
                for (int ni = 0; ni < 4; ni++) mma8(acc[mi][ni], af[mi], bf[ni]);
        }
        __syncthreads();
    }

    // epilogue: e[m] += sum_j fc2[j]*tanh(C+sv)
    float* svs = sA;   // [32][132]
    float* fc2s = sB;  // [128]
    for (int idx = tid; idx < 32 * 128; idx += 256)
        svs[(idx >> 7) * 132 + (idx & 127)] = g_sv[att * 32768 + (idx >> 7) * 1024 + n0 + (idx & 127)];
    if (tid < 128) fc2s[tid] = fc2[n0 + tid];
    __syncthreads();

    float part[8] = {0, 0, 0, 0, 0, 0, 0, 0};
    #pragma unroll
    for (int mi = 0; mi < 4; mi++) {
        const int bA = (mi & 1) * 16 + g, bB = bA + 8;
        #pragma unroll
        for (int ni = 0; ni < 4; ni++) {
            const int j = wn * 32 + ni * 8 + 2 * tg;
            const float f0 = fc2s[j], f1 = fc2s[j + 1];
            part[mi * 2] += f0 * tanh_fast(acc[mi][ni][0] + svs[bA * 132 + j])
                          + f1 * tanh_fast(acc[mi][ni][1] + svs[bA * 132 + j + 1]);
            part[mi * 2 + 1] += f0 * tanh_fast(acc[mi][ni][2] + svs[bB * 132 + j])
                              + f1 * tanh_fast(acc[mi][ni][3] + svs[bB * 132 + j + 1]);
        }
    }
    #pragma unroll
    for (int o = 1; o <= 2; o <<= 1)
        #pragma unroll
        for (int r = 0; r < 8; r++) part[r] += __shfl_xor_sync(~0u, part[r], o);
    if (tg == 0) {
        #pragma unroll
        for (int mi = 0; mi < 4; mi++) {
            atomicAdd(&g_e[att * 16384 + m0 + wm * 64 + mi * 16 + g], part[mi * 2]);
            atomicAdd(&g_e[att * 16384 + m0 + wm * 64 + mi * 16 + g + 8], part[mi * 2 + 1]);
        }
    }
}

// ---------- softmax over s ----------
__global__ void softmax_kernel() {
    const int b = blockIdx.x, att = blockIdx.y, s = threadIdx.x;
    __shared__ float red[512];
    const float v = g_e[att * 16384 + s * 32 + b];
    red[s] = v; __syncthreads();
    for (int o = 256; o > 0; o >>= 1) { if (s < o) red[s] = fmaxf(red[s], red[s + o]); __syncthreads(); }
    const float m = red[0]; __syncthreads();
    const float ex = expf(v - m);
    red[s] = ex; __syncthreads();
    for (int o = 256; o > 0; o >>= 1) { if (s < o) red[s] += red[s + o]; __syncthreads(); }
    g_alpha[att * 16384 + b * 512 + s] = ex / red[0];
}

// ---------- context = alpha @ enc ----------
__global__ void ctx_kernel(const float* __restrict__ enc, const float* __restrict__ encp) {
    const int b = blockIdx.x, att = blockIdx.y, tid = threadIdx.x;
    const float* E = att ? encp : enc;
    __shared__ float al[512];
    al[tid] = g_alpha[att * 16384 + b * 512 + tid];
    al[tid + 256] = g_alpha[att * 16384 + b * 512 + tid + 256];
    __syncthreads();
    float a0 = 0, a1 = 0, a2 = 0, a3 = 0;
    for (int s = 0; s < 512; s++) {
        const float a = al[s];
        const float* row = E + ((size_t)s * 32 + b) * 1024 + tid;
        a0 += a * row[0]; a1 += a * row[256]; a2 += a * row[512]; a3 += a * row[768];
    }
    float* c = g_ctx + att * 32768 + b * 1024 + tid;
    c[0] = a0; c[256] = a1; c[512] = a2; c[768] = a3;
}

// ---------- attn_fc: out1 = relu([h1, ctx0, ctx1] @ W^T + b) ----------
__global__ void attnfc_kernel(const float* __restrict__ W, const float* __restrict__ bias) {
    const int j = blockIdx.x;
    __shared__ float ws[3072];
    for (int k = threadIdx.x; k < 3072; k += 256) ws[k] = W[(size_t)j * 3072 + k];
    __syncthreads();
    const int lane = threadIdx.x & 31, wid = threadIdx.x >> 5;
    for (int b = wid; b < 32; b += 8) {
        const float* f0 = g_h1 + (size_t)b * 1024;
        const float* c1 = g_ctx + (size_t)b * 1024;
        const float* c2 = g_ctx + 32768 + (size_t)b * 1024;
        float a = 0;
        for (int k = lane; k < 1024; k += 32)
            a += ws[k] * f0[k] + ws[1024 + k] * c1[k] + ws[2048 + k] * c2[k];
        #pragma unroll
        for (int o = 16; o; o >>= 1) a += __shfl_xor_sync(~0u, a, o);
        if (lane == 0) g_out1[b * 1024 + j] = fmaxf(a + bias[j], 0.f);
    }
}

// ---------- logits: 3xTF32 mma, M=32000 N=32 K=1024 ----------
__global__ __launch_bounds__(256) void logits_kernel(const float* __restrict__ fcw,
                                                     const float* __restrict__ fcb,
                                                     float* __restrict__ out) {
    const int m0 = blockIdx.x * 128;
    __shared__ float Ah[128 * 36], Al[128 * 36], Bh[32 * 36], Bl[32 * 36];
    const int tid = threadIdx.x, lane = tid & 31, wid = tid >> 5;
    const int g = lane >> 2, tg = lane & 3;
    float acc[4][4];
    #pragma unroll
    for (int i = 0; i < 4; i++) { acc[i][0] = acc[i][1] = acc[i][2] = acc[i][3] = 0.f; }

    const int ldrow = tid >> 3, ldc = (tid & 7) * 4;
    for (int t = 0; t < 32; t++) {
        #pragma unroll
        for (int i = 0; i < 4; i++) {
            float4 v = *(const float4*)(fcw + (size_t)(m0 + ldrow + i * 32) * 1024 + t * 32 + ldc);
            float4 h, l;
            h.x = to_tf32(v.x); h.y = to_tf32(v.y); h.z = to_tf32(v.z); h.w = to_tf32(v.w);
            l.x = v.x - h.x; l.y = v.y - h.y; l.z = v.z - h.z; l.w = v.w - h.w;
            *(float4*)&Ah[(ldrow + i * 32) * 36 + ldc] = h;
            *(float4*)&Al[(ldrow + i * 32) * 36 + ldc] = l;
        }
        {
            float4 v = *(const float4*)(g_out1 + (size_t)ldrow * 1024 + t * 32 + ldc);
            float4 h, l;
            h.x = to_tf32(v.x); h.y = to_tf32(v.y); h.z = to_tf32(v.z); h.w = to_tf32(v.w);
            l.x = v.x - h.x; l.y = v.y - h.y; l.z = v.z - h.z; l.w = v.w - h.w;
            *(float4*)&Bh[ldrow * 36 + ldc] = h;
            *(float4*)&Bl[ldrow * 36 + ldc] = l;
        }
        __syncthreads();
        #pragma unroll
        for (int kk = 0; kk < 32; kk += 8) {
            uint32_t ah[4], al4[4];
            const int r = (wid * 16 + g) * 36 + kk + tg;
            ah[0] = __float_as_uint(Ah[r]); ah[1] = __float_as_uint(Ah[r + 8 * 36]);
            ah[2] = __float_as_uint(Ah[r + 4]); ah[3] = __float_as_uint(Ah[r + 8 * 36 + 4]);
            al4[0] = __float_as_uint(Al[r]); al4[1] = __float_as_uint(Al[r + 8 * 36]);
            al4[2] = __float_as_uint(Al[r + 4]); al4[3] = __float_as_uint(Al[r + 8 * 36 + 4]);
            #pragma unroll
            for (int ni = 0; ni < 4; ni++) {
                const int rb = (ni * 8 + g) * 36 + kk + tg;
                uint32_t bh[2] = {__float_as_uint(Bh[rb]), __float_as_uint(Bh[rb + 4])};
                uint32_t bl[2] = {__float_as_uint(Bl[rb]), __float_as_uint(Bl[rb + 4])};
                mma8(acc[ni], ah, bh);
                mma8(acc[ni], ah, bl);
                mma8(acc[ni], al4, bh);
            }
        }
        __syncthreads();
    }
    const int j0 = m0 + wid * 16 + g;
    const float b0f = fcb[j0], b8f = fcb[j0 + 8];
    #pragma unroll
    for (int ni = 0; ni < 4; ni++) {
        const int b = ni * 8 + 2 * tg;
        out[(size_t)b * 32000 + j0] = acc[ni][0] + b0f;
        out[(size_t)(b + 1) * 32000 + j0] = acc[ni][1] + b0f;
        out[(size_t)b * 32000 + j0 + 8] = acc[ni][2] + b8f;
        out[(size_t)(b + 1) * 32000 + j0 + 8] = acc[ni][3] + b8f;
    }
}

extern "C" void kernel_launch(void* const* d_in, const int* in_sizes, int n_in,
                              void* d_out, int out_size) {
    (void)in_sizes; (void)n_in; (void)out_size;
    const int* ids = (const int*)d_in[0];
    const float* hidden = (const float*)d_in[1];
    const float* enc = (const float*)d_in[2];
    const float* encp = (const float*)d_in[3];
    const float* emb = (const float*)d_in[4];
    const float* Wih0 = (const float*)d_in[5];
    const float* Whh0 = (const float*)d_in[6];
    const float* bih0 = (const float*)d_in[7];
    const float* bhh0 = (const float*)d_in[8];
    const float* Wih1 = (const float*)d_in[9];
    const float* Whh1 = (const float*)d_in[10];
    const float* bih1 = (const float*)d_in[11];
    const float* bhh1 = (const float*)d_in[12];
    const float* afc1w = (const float*)d_in[13];
    const float* afc1b = (const float*)d_in[14];
    const float* afc2w = (const float*)d_in[15];
    const float* pfc1w = (const float*)d_in[17];
    const float* pfc1b = (const float*)d_in[18];
    const float* pfc2w = (const float*)d_in[19];
    const float* nfcw = (const float*)d_in[21];
    const float* nfcb = (const float*)d_in[22];
    const float* fcw = (const float*)d_in[23];
    const float* fcb = (const float*)d_in[24];
    float* out = (float*)d_out;
    float* out_nh = out + 1024000;  // logits [1,32,32000] then new_hidden [2,32,1024]

    zero_kernel<<<128, 256>>>();
    gru_kernel<<<1024, 256>>>(Wih0, Whh0, bih0, bhh0, ids, emb, hidden, 0, out_nh);
    gru_kernel<<<1024, 256>>>(Wih1, Whh1, bih1, bhh1, ids, emb, hidden, 1, out_nh);
    sv_kernel<<<dim3(256, 2), 256>>>(afc1w, afc1b, pfc1w, pfc1b);
    big_att_kernel<<<dim3(8, 128, 2), 256>>>(enc, encp, afc1w, pfc1w, afc2w, pfc2w);
    softmax_kernel<<<dim3(32, 2), 512>>>();
    ctx_kernel<<<dim3(32, 2), 256>>>(enc, encp);
    attnfc_kernel<<<1024, 256>>>(nfcw, nfcb);
    logits_kernel<<<250, 256>>>(fcw, fcb, out);
}

// round 4
// speedup vs baseline: 1.2761x; 1.2761x over previous
#include <cuda_runtime.h>
#include <cstdint>
#include <cstddef>

#define DEV __device__ __forceinline__

// ---------------- scratch arena (accumulators first; first ZERO_COUNT zeroed) ----------------
__device__ __align__(256) float g_scratch[819200];
#define P_E      (g_scratch + 0)        // [att][s*32+b]   32768
#define O_GI0    32768                   // [3j][b]         98304
#define O_GH0    131072
#define O_GI1    229376
#define O_GH1    327680
#define O_SV2    425984                  // [att][j*32+b]   65536
#define O_FC     491520                  // [j*32+b]        32768
#define O_XCAT   524288                  // [b][3072]       98304
#define ZERO_COUNT 622592
#define O_X0     622592                  // [b][1024]
#define O_H0     655360                  // [b][1024]
#define O_SCAT   688128                  // [b][2048]
#define O_ALPHA  753664                  // [att][b][s]
#define O_OUT1   786432                  // [b][1024]
#define P_SV2    (g_scratch + O_SV2)
#define P_XCAT   (g_scratch + O_XCAT)
#define P_ALPHA  (g_scratch + O_ALPHA)
#define P_OUT1   (g_scratch + O_OUT1)

DEV float to_tf32(float x) { uint32_t u; asm("cvt.rna.tf32.f32 %0,%1;" : "=r"(u) : "f"(x)); return __uint_as_float(u); }
DEV float tanh_fast(float x) { float y; asm("tanh.approx.f32 %0,%1;" : "=f"(y) : "f"(x)); return y; }
DEV float sigm(float x) { return 1.f / (1.f + expf(-x)); }
DEV void mma8(float c[4], const uint32_t a[4], const uint32_t b[2]) {
    asm volatile("mma.sync.aligned.m16n8k8.row.col.f32.tf32.tf32.f32 "
                 "{%0,%1,%2,%3},{%4,%5,%6,%7},{%8,%9},{%0,%1,%2,%3};"
                 : "+f"(c[0]), "+f"(c[1]), "+f"(c[2]), "+f"(c[3])
                 : "r"(a[0]), "r"(a[1]), "r"(a[2]), "r"(a[3]), "r"(b[0]), "r"(b[1]));
}

__global__ void zero_kernel() { g_scratch[blockIdx.x * 256 + threadIdx.x] = 0.f; }

__global__ void pack_x0(const int* __restrict__ ids, const float* __restrict__ emb) {
    int t = blockIdx.x * 256 + threadIdx.x;  // 32768
    g_scratch[O_X0 + t] = emb[(size_t)ids[t >> 10] * 1024 + (t & 1023)];
}

// ---------- generic weight-streaming GEMM (3xTF32): out[j*32+b] += sum_k W[j,k]*X[b,k] ----------
// grid (M/128, nsets, ksplit). Scratch operands via offsets; external X via pointer.
__global__ __launch_bounds__(256) void gemm32_kernel(
    const float* __restrict__ Wa, const float* __restrict__ biasa, const float* __restrict__ Xae, int xaoff, int oaoff,
    const float* __restrict__ Wb, const float* __restrict__ biasb, const float* __restrict__ Xbe, int xboff, int oboff,
    int ldw, int K) {
    const float* W = blockIdx.y ? Wb : Wa;
    const float* bias = blockIdx.y ? biasb : biasa;
    const float* X = blockIdx.y ? (Xbe ? Xbe : g_scratch + xboff) : (Xae ? Xae : g_scratch + xaoff);
    float* out = g_scratch + (blockIdx.y ? oboff : oaoff);
    const int m0 = blockIdx.x * 128;
    const int Kc = K / gridDim.z;
    const int k0 = blockIdx.z * Kc;

    __shared__ float Ah[128 * 36], Al[128 * 36], Bh[32 * 36], Bl[32 * 36];
    const int tid = threadIdx.x, lane = tid & 31, wid = tid >> 5;
    const int g = lane >> 2, tg = lane & 3;
    float acc[4][4];
    #pragma unroll
    for (int i = 0; i < 4; i++) { acc[i][0] = acc[i][1] = acc[i][2] = acc[i][3] = 0.f; }

    const int ldrow = tid >> 3, ldc = (tid & 7) * 4;
    for (int t = 0; t < Kc / 32; t++) {
        #pragma unroll
        for (int i = 0; i < 4; i++) {
            float4 v = *(const float4*)(W + (size_t)(m0 + ldrow + i * 32) * ldw + k0 + t * 32 + ldc);
            float4 h, l;
            h.x = to_tf32(v.x); h.y = to_tf32(v.y); h.z = to_tf32(v.z); h.w = to_tf32(v.w);
            l.x = v.x - h.x; l.y = v.y - h.y; l.z = v.z - h.z; l.w = v.w - h.w;
            *(float4*)&Ah[(ldrow + i * 32) * 36 + ldc] = h;
            *(float4*)&Al[(ldrow + i * 32) * 36 + ldc] = l;
        }
        {
            float4 v = *(const float4*)(X + (size_t)ldrow * K + k0 + t * 32 + ldc);
            float4 h, l;
            h.x = to_tf32(v.x); h.y = to_tf32(v.y); h.z = to_tf32(v.z); h.w = to_tf32(v.w);
            l.x = v.x - h.x; l.y = v.y - h.y; l.z = v.z - h.z; l.w = v.w - h.w;
            *(float4*)&Bh[ldrow * 36 + ldc] = h;
            *(float4*)&Bl[ldrow * 36 + ldc] = l;
        }
        __syncthreads();
        #pragma unroll
        for (int kk = 0; kk < 32; kk += 8) {
            uint32_t ah[4], al4[4];
            const int r = (wid * 16 + g) * 36 + kk + tg;
            ah[0] = __float_as_uint(Ah[r]); ah[1] = __float_as_uint(Ah[r + 8 * 36]);
            ah[2] = __float_as_uint(Ah[r + 4]); ah[3] = __float_as_uint(Ah[r + 8 * 36 + 4]);
            al4[0] = __float_as_uint(Al[r]); al4[1] = __float_as_uint(Al[r + 8 * 36]);
            al4[2] = __float_as_uint(Al[r + 4]); al4[3] = __float_as_uint(Al[r + 8 * 36 + 4]);
            #pragma unroll
            for (int ni = 0; ni < 4; ni++) {
                const int rb = (ni * 8 + g) * 36 + kk + tg;
                uint32_t bh[2] = {__float_as_uint(Bh[rb]), __float_as_uint(Bh[rb + 4])};
                uint32_t bl[2] = {__float_as_uint(Bl[rb]), __float_as_uint(Bl[rb + 4])};
                mma8(acc[ni], ah, bh);
                mma8(acc[ni], ah, bl);
                mma8(acc[ni], al4, bh);
            }
        }
        __syncthreads();
    }
    const int j0 = m0 + wid * 16 + g;
    float b0f = 0.f, b8f = 0.f;
    if (bias && blockIdx.z == 0) { b0f = bias[j0]; b8f = bias[j0 + 8]; }
    #pragma unroll
    for (int ni = 0; ni < 4; ni++) {
        const int b = ni * 8 + 2 * tg;
        atomicAdd(&out[j0 * 32 + b], acc[ni][0] + b0f);
        atomicAdd(&out[j0 * 32 + b + 1], acc[ni][1] + b0f);
        atomicAdd(&out[(j0 + 8) * 32 + b], acc[ni][2] + b8f);
        atomicAdd(&out[(j0 + 8) * 32 + b + 1], acc[ni][3] + b8f);
    }
}

// ---------- GRU elementwise combine ----------
__global__ void gru_combine(int gioff, int ghoff, const float* __restrict__ bih,
                            const float* __restrict__ bhh, const float* __restrict__ hprev,
                            int d0off, int s0, int d1off, int s1, float* __restrict__ out_nh) {
    const int t = blockIdx.x * 256 + threadIdx.x;  // 32768
    const int j = t >> 5, b = t & 31;
    const float* gi = g_scratch + gioff;
    const float* gh = g_scratch + ghoff;
    const float r = sigm(gi[j * 32 + b] + bih[j] + gh[j * 32 + b] + bhh[j]);
    const float z = sigm(gi[(1024 + j) * 32 + b] + bih[1024 + j] + gh[(1024 + j) * 32 + b] + bhh[1024 + j]);
    const float n = tanhf(gi[(2048 + j) * 32 + b] + bih[2048 + j] + r * (gh[(2048 + j) * 32 + b] + bhh[2048 + j]));
    const float h = (1.f - z) * n + z * hprev[b * 1024 + j];
    g_scratch[d0off + b * s0 + j] = h;
    g_scratch[d1off + b * s1 + j] = h;
    out_nh[b * 1024 + j] = h;
}

// ---------- big fused GEMM + tanh/fc2 epilogue -> e ----------
__global__ __launch_bounds__(256) void big_att_kernel(
    const float* __restrict__ enc, const float* __restrict__ encp,
    const float* __restrict__ fc1a, const float* __restrict__ fc1p,
    const float* __restrict__ fc2a, const float* __restrict__ fc2p) {
    const int att = blockIdx.z;
    const float* __restrict__ A = att ? encp : enc;
    const float* __restrict__ W = att ? fc1p : fc1a;
    const float* __restrict__ fc2 = att ? fc2p : fc2a;
    const int m0 = blockIdx.y * 128, n0 = blockIdx.x * 128;

    __shared__ float sA[128 * 36], sB[128 * 36];
    const int tid = threadIdx.x, lane = tid & 31, wid = tid >> 5;
    const int wm = wid >> 2, wn = wid & 3, g = lane >> 2, tg = lane & 3;

    float acc[4][4][4];
    #pragma unroll
    for (int i = 0; i < 4; i++)
        #pragma unroll
        for (int j = 0; j < 4; j++) { acc[i][j][0] = acc[i][j][1] = acc[i][j][2] = acc[i][j][3] = 0.f; }

    const int ldrow = tid >> 3, ldc = (tid & 7) * 4;
    const float* Ap = A + (size_t)(m0 + ldrow) * 1024 + ldc;
    const float* Wp = W + (size_t)(n0 + ldrow) * 3072 + 2048 + ldc;

    float4 ra[4], rb[4];
    #pragma unroll
    for (int i = 0; i < 4; i++) {
        ra[i] = *(const float4*)(Ap + (size_t)i * 32 * 1024);
        rb[i] = *(const float4*)(Wp + (size_t)i * 32 * 3072);
    }
    for (int t = 0; t < 32; t++) {
        #pragma unroll
        for (int i = 0; i < 4; i++) {
            float4 a = ra[i], b = rb[i];
            a.x = to_tf32(a.x); a.y = to_tf32(a.y); a.z = to_tf32(a.z); a.w = to_tf32(a.w);
            b.x = to_tf32(b.x); b.y = to_tf32(b.y); b.z = to_tf32(b.z); b.w = to_tf32(b.w);
            *(float4*)&sA[(ldrow + i * 32) * 36 + ldc] = a;
            *(float4*)&sB[(ldrow + i * 32) * 36 + ldc] = b;
        }
        __syncthreads();
        if (t + 1 < 32) {
            #pragma unroll
            for (int i = 0; i < 4; i++) {
                ra[i] = *(const float4*)(Ap + (size_t)i * 32 * 1024 + (t + 1) * 32);
                rb[i] = *(const float4*)(Wp + (size_t)i * 32 * 3072 + (t + 1) * 32);
            }
        }
        #pragma unroll
        for (int kk = 0; kk < 32; kk += 8) {
            uint32_t af[4][4], bf[4][2];
            #pragma unroll
            for (int mi = 0; mi < 4; mi++) {
                const int r = (wm * 64 + mi * 16 + g) * 36 + kk + tg;
                af[mi][0] = __float_as_uint(sA[r]);
                af[mi][1] = __float_as_uint(sA[r + 8 * 36]);
                af[mi][2] = __float_as_uint(sA[r + 4]);
                af[mi][3] = __float_as_uint(sA[r + 8 * 36 + 4]);
            }
            #pragma unroll
            for (int ni = 0; ni < 4; ni++) {
                const int r = (wn * 32 + ni * 8 + g) * 36 + kk + tg;
                bf[ni][0] = __float_as_uint(sB[r]);
                bf[ni][1] = __float_as_uint(sB[r + 4]);
            }
            #pragma unroll
            for (int mi = 0; mi < 4; mi++)
                #pragma unroll
                for (int ni = 0; ni < 4; ni++) mma8(acc[mi][ni], af[mi], bf[ni]);
        }
        __syncthreads();
    }

    float* svs = sA;   // [32][132]
    float* fc2s = sB;  // [128]
    for (int idx = tid; idx < 32 * 128; idx += 256)
        svs[(idx >> 7) * 132 + (idx & 127)] = P_SV2[att * 32768 + (n0 + (idx & 127)) * 32 + (idx >> 7)];
    if (tid < 128) fc2s[tid] = fc2[n0 + tid];
    __syncthreads();

    float part[8] = {0, 0, 0, 0, 0, 0, 0, 0};
    #pragma unroll
    for (int mi = 0; mi < 4; mi++) {
        const int bA = (mi & 1) * 16 + g, bB = bA + 8;
        #pragma unroll
        for (int ni = 0; ni < 4; ni++) {
            const int j = wn * 32 + ni * 8 + 2 * tg;
            const float f0 = fc2s[j], f1 = fc2s[j + 1];
            part[mi * 2] += f0 * tanh_fast(acc[mi][ni][0] + svs[bA * 132 + j])
                          + f1 * tanh_fast(acc[mi][ni][1] + svs[bA * 132 + j + 1]);
            part[mi * 2 + 1] += f0 * tanh_fast(acc[mi][ni][2] + svs[bB * 132 + j])
                              + f1 * tanh_fast(acc[mi][ni][3] + svs[bB * 132 + j + 1]);
        }
    }
    #pragma unroll
    for (int o = 1; o <= 2; o <<= 1)
        #pragma unroll
        for (int r = 0; r < 8; r++) part[r] += __shfl_xor_sync(~0u, part[r], o);
    if (tg == 0) {
        #pragma unroll
        for (int mi = 0; mi < 4; mi++) {
            atomicAdd(&P_E[att * 16384 + m0 + wm * 64 + mi * 16 + g], part[mi * 2]);
            atomicAdd(&P_E[att * 16384 + m0 + wm * 64 + mi * 16 + g + 8], part[mi * 2 + 1]);
        }
    }
}

// ---------- softmax over s ----------
__global__ void softmax_kernel() {
    const int b = blockIdx.x, att = blockIdx.y, s = threadIdx.x;
    __shared__ float red[512];
    const float v = P_E[att * 16384 + s * 32 + b];
    red[s] = v; __syncthreads();
    for (int o = 256; o > 0; o >>= 1) { if (s < o) red[s] = fmaxf(red[s], red[s + o]); __syncthreads(); }
    const float m = red[0]; __syncthreads();
    const float ex = expf(v - m);
    red[s] = ex; __syncthreads();
    for (int o = 256; o > 0; o >>= 1) { if (s < o) red[s] += red[s + o]; __syncthreads(); }
    P_ALPHA[att * 16384 + b * 512 + s] = ex / red[0];
}

// ---------- context (s-split), accumulate into xcat cols 1024..3071 ----------
__global__ void ctx_kernel(const float* __restrict__ enc, const float* __restrict__ encp) {
    const int b = blockIdx.x, att = blockIdx.y, s0 = blockIdx.z * 64, tid = threadIdx.x;
    const float* E = att ? encp : enc;
    __shared__ float al[64];
    if (tid < 64) al[tid] = P_ALPHA[att * 16384 + b * 512 + s0 + tid];
    __syncthreads();
    float a0 = 0, a1 = 0, a2 = 0, a3 = 0;
    #pragma unroll 4
    for (int i = 0; i < 64; i++) {
        const float a = al[i];
        const float* row = E + ((size_t)(s0 + i) * 32 + b) * 1024 + tid;
        a0 += a * row[0]; a1 += a * row[256]; a2 += a * row[512]; a3 += a * row[768];
    }
    float* c = P_XCAT + b * 3072 + 1024 + att * 1024 + tid;
    atomicAdd(c, a0); atomicAdd(c + 256, a1); atomicAdd(c + 512, a2); atomicAdd(c + 768, a3);
}

// ---------- relu + transpose ----------
__global__ void relu_tr_kernel() {
    const int t = blockIdx.x * 256 + threadIdx.x;
    P_OUT1[(t & 31) * 1024 + (t >> 5)] = fmaxf(g_scratch[O_FC + t], 0.f);
}

// ---------- logits: 3xTF32 mma, M=32000 N=32 K=1024 ----------
__global__ __launch_bounds__(256) void logits_kernel(const float* __restrict__ fcw,
                                                     const float* __restrict__ fcb,
                                                     float* __restrict__ out) {
    const int m0 = blockIdx.x * 128;
    __shared__ float Ah[128 * 36], Al[128 * 36], Bh[32 * 36], Bl[32 * 36];
    const int tid = threadIdx.x, lane = tid & 31, wid = tid >> 5;
    const int g = lane >> 2, tg = lane & 3;
    float acc[4][4];
    #pragma unroll
    for (int i = 0; i < 4; i++) { acc[i][0] = acc[i][1] = acc[i][2] = acc[i][3] = 0.f; }

    const int ldrow = tid >> 3, ldc = (tid & 7) * 4;
    for (int t = 0; t < 32; t++) {
        #pragma unroll
        for (int i = 0; i < 4; i++) {
            float4 v = *(const float4*)(fcw + (size_t)(m0 + ldrow + i * 32) * 1024 + t * 32 + ldc);
            float4 h, l;
            h.x = to_tf32(v.x); h.y = to_tf32(v.y); h.z = to_tf32(v.z); h.w = to_tf32(v.w);
            l.x = v.x - h.x; l.y = v.y - h.y; l.z = v.z - h.z; l.w = v.w - h.w;
            *(float4*)&Ah[(ldrow + i * 32) * 36 + ldc] = h;
            *(float4*)&Al[(ldrow + i * 32) * 36 + ldc] = l;
        }
        {
            float4 v = *(const float4*)(P_OUT1 + (size_t)ldrow * 1024 + t * 32 + ldc);
            float4 h, l;
            h.x = to_tf32(v.x); h.y = to_tf32(v.y); h.z = to_tf32(v.z); h.w = to_tf32(v.w);
            l.x = v.x - h.x; l.y = v.y - h.y; l.z = v.z - h.z; l.w = v.w - h.w;
            *(float4*)&Bh[ldrow * 36 + ldc] = h;
            *(float4*)&Bl[ldrow * 36 + ldc] = l;
        }
        __syncthreads();
        #pragma unroll
        for (int kk = 0; kk < 32; kk += 8) {
            uint32_t ah[4], al4[4];
            const int r = (wid * 16 + g) * 36 + kk + tg;
            ah[0] = __float_as_uint(Ah[r]); ah[1] = __float_as_uint(Ah[r + 8 * 36]);
            ah[2] = __float_as_uint(Ah[r + 4]); ah[3] = __float_as_uint(Ah[r + 8 * 36 + 4]);
            al4[0] = __float_as_uint(Al[r]); al4[1] = __float_as_uint(Al[r + 8 * 36]);
            al4[2] = __float_as_uint(Al[r + 4]); al4[3] = __float_as_uint(Al[r + 8 * 36 + 4]);
            #pragma unroll
            for (int ni = 0; ni < 4; ni++) {
                const int rb = (ni * 8 + g) * 36 + kk + tg;
                uint32_t bh[2] = {__float_as_uint(Bh[rb]), __float_as_uint(Bh[rb + 4])};
                uint32_t bl[2] = {__float_as_uint(Bl[rb]), __float_as_uint(Bl[rb + 4])};
                mma8(acc[ni], ah, bh);
                mma8(acc[ni], ah, bl);
                mma8(acc[ni], al4, bh);
            }
        }
        __syncthreads();
    }
    const int j0 = m0 + wid * 16 + g;
    const float b0f = fcb[j0], b8f = fcb[j0 + 8];
    #pragma unroll
    for (int ni = 0; ni < 4; ni++) {
        const int b = ni * 8 + 2 * tg;
        out[(size_t)b * 32000 + j0] = acc[ni][0] + b0f;
        out[(size_t)(b + 1) * 32000 + j0] = acc[ni][1] + b0f;
        out[(size_t)b * 32000 + j0 + 8] = acc[ni][2] + b8f;
        out[(size_t)(b + 1) * 32000 + j0 + 8] = acc[ni][3] + b8f;
    }
}

extern "C" void kernel_launch(void* const* d_in, const int* in_sizes, int n_in,
                              void* d_out, int out_size) {
    (void)in_sizes; (void)n_in; (void)out_size;
    const int* ids = (const int*)d_in[0];
    const float* hidden = (const float*)d_in[1];
    const float* enc = (const float*)d_in[2];
    const float* encp = (const float*)d_in[3];
    const float* emb = (const float*)d_in[4];
    const float* Wih0 = (const float*)d_in[5];
    const float* Whh0 = (const float*)d_in[6];
    const float* bih0 = (const float*)d_in[7];
    const float* bhh0 = (const float*)d_in[8];
    const float* Wih1 = (const float*)d_in[9];
    const float* Whh1 = (const float*)d_in[10];
    const float* bih1 = (const float*)d_in[11];
    const float* bhh1 = (const float*)d_in[12];
    const float* afc1w = (const float*)d_in[13];
    const float* afc1b = (const float*)d_in[14];
    const float* afc2w = (const float*)d_in[15];
    const float* pfc1w = (const float*)d_in[17];
    const float* pfc1b = (const float*)d_in[18];
    const float* pfc2w = (const float*)d_in[19];
    const float* nfcw = (const float*)d_in[21];
    const float* nfcb = (const float*)d_in[22];
    const float* fcw = (const float*)d_in[23];
    const float* fcb = (const float*)d_in[24];
    float* out = (float*)d_out;
    float* out_nh = out + 1024000;  // logits [1,32,32000] then new_hidden [2,32,1024]

    zero_kernel<<<ZERO_COUNT / 256, 256>>>();
    pack_x0<<<128, 256>>>(ids, emb);
    // GRU layer 0: gi0 = Wih0 @ x0^T ; gh0 = Whh0 @ hidden[0]^T
    gemm32_kernel<<<dim3(24, 2, 8), 256>>>(Wih0, nullptr, nullptr, O_X0, O_GI0,
                                           Whh0, nullptr, hidden, 0, O_GH0, 1024, 1024);
    gru_combine<<<128, 256>>>(O_GI0, O_GH0, bih0, bhh0, hidden, O_H0, 1024, O_SCAT, 2048, out_nh);
    // GRU layer 1
    gemm32_kernel<<<dim3(24, 2, 8), 256>>>(Wih1, nullptr, nullptr, O_H0, O_GI1,
                                           Whh1, nullptr, hidden + 32768, 0, O_GH1, 1024, 1024);
    gru_combine<<<128, 256>>>(O_GI1, O_GH1, bih1, bhh1, hidden + 32768,
                              O_XCAT, 3072, O_SCAT + 1024, 2048, out_nh + 32768);
    // state-part of both attention fc1 (+bias)
    gemm32_kernel<<<dim3(8, 2, 8), 256>>>(afc1w, afc1b, nullptr, O_SCAT, O_SV2,
                                          pfc1w, pfc1b, nullptr, O_SCAT, O_SV2 + 32768, 3072, 2048);
    big_att_kernel<<<dim3(8, 128, 2), 256>>>(enc, encp, afc1w, pfc1w, afc2w, pfc2w);
    softmax_kernel<<<dim3(32, 2), 512>>>();
    ctx_kernel<<<dim3(32, 2, 8), 256>>>(enc, encp);
    // attn_fc on [h1, ctx, ctx_p]
    gemm32_kernel<<<dim3(8, 1, 8), 256>>>(nfcw, nfcb, nullptr, O_XCAT, O_FC,
                                          nfcw, nfcb, nullptr, O_XCAT, O_FC, 3072, 3072);
    relu_tr_kernel<<<128, 256>>>();
    logits_kernel<<<250, 256>>>(fcw, fcb, out);
}